// round 16
// baseline (speedup 1.0000x reference)
#include <cuda_runtime.h>
#include <cuda_bf16.h>
#include <cstdint>

#define NG 128
#define NPMAX 200000
#define NRMAX 400000
#define EMAX 2000000

// ---- static scratch ----
__device__ __align__(16) uint32_t g_p_y[NPMAX * 32];   // bf16x2: 64 cols -> 32 words
__device__ __align__(16) uint32_t g_r_y[NRMAX * 32];
__device__ int   g_p_cnt[NPMAX];
__device__ int   g_r_cnt[NRMAX];
__device__ int   g_p_off[NPMAX];
__device__ int   g_r_off[NRMAX];
__device__ int   g_p_pos[NPMAX];
__device__ int   g_r_pos[NRMAX];
__device__ int   g_p_srcs[EMAX];
__device__ int   g_r_srcs[EMAX];
__device__ int   g_bs[256];          // [0..127] p-blocks, [128..255] r-blocks
__device__ float g_pool[NG * 128];
__device__ float g_cnt[2 * NG];
__device__ __align__(16) __nv_bfloat16 g_pWhi[64 * 1280];
__device__ __align__(16) __nv_bfloat16 g_rWhi[64 * 128];

__device__ __forceinline__ uint32_t smem_u32(const void* p) {
    uint32_t a;
    asm("{ .reg .u64 t; cvta.to.shared.u64 t, %1; cvt.u32.u64 %0, t; }" : "=r"(a) : "l"(p));
    return a;
}

__device__ __forceinline__ void ldm_x4(uint32_t* r, uint32_t addr) {
    asm volatile("ldmatrix.sync.aligned.m8n8.x4.shared.b16 {%0,%1,%2,%3}, [%4];"
                 : "=r"(r[0]), "=r"(r[1]), "=r"(r[2]), "=r"(r[3]) : "r"(addr));
}

__device__ __forceinline__ void mma_bf16(float* d, const uint32_t* a, uint32_t b0, uint32_t b1) {
    asm volatile(
        "mma.sync.aligned.m16n8k16.row.col.f32.bf16.bf16.f32 "
        "{%0,%1,%2,%3}, {%4,%5,%6,%7}, {%8,%9}, {%0,%1,%2,%3};"
        : "+f"(d[0]), "+f"(d[1]), "+f"(d[2]), "+f"(d[3])
        : "r"(a[0]), "r"(a[1]), "r"(a[2]), "r"(a[3]), "r"(b0), "r"(b1));
}

__device__ __forceinline__ void cvt_hilo(float x, float y, uint32_t& hi, uint32_t& lo) {
    __nv_bfloat162 h = __float22bfloat162_rn(make_float2(x, y));
    float hx = __low2float(h), hy = __high2float(h);
    __nv_bfloat162 l = __float22bfloat162_rn(make_float2(x - hx, y - hy));
    hi = *(uint32_t*)&h;
    lo = *(uint32_t*)&l;
}

// ---------------------------------------------------------------------------
__global__ void k_init(int np, int nr,
                       const float* __restrict__ pW, const float* __restrict__ rW,
                       int Kp, int KpPad, int Kr, int KrPad) {
    int i = blockIdx.x * blockDim.x + threadIdx.x;
    if (i < np) g_p_cnt[i] = 0;
    if (i < nr) g_r_cnt[i] = 0;
    if (i < NG * 128) g_pool[i] = 0.0f;
    if (i < 2 * NG) g_cnt[i] = 0.0f;
    if (i < 64 * KpPad) {
        int n = i / KpPad, k = i % KpPad;
        g_pWhi[i] = __float2bfloat16_rn((k < Kp) ? pW[k * 64 + n] : 0.0f);
    }
    if (i < 64 * KrPad) {
        int n = i / KrPad, k = i % KrPad;
        g_rWhi[i] = __float2bfloat16_rn((k < Kr) ? rW[k * 64 + n] : 0.0f);
    }
}

__global__ void k_count(const int* __restrict__ dst, int E, int* __restrict__ cnt) {
    int e = blockIdx.x * blockDim.x + threadIdx.x;
    if (e < E) atomicAdd(&cnt[dst[e]], 1);
}

// ---------------------------------------------------------------------------
// fused exclusive scans
// ---------------------------------------------------------------------------
__global__ __launch_bounds__(256) void k_s1f(int nbP, int Np, int Nr) {
    const int* cnt;
    int n, b;
    int* bs;
    if ((int)blockIdx.x < nbP) { cnt = g_p_cnt; n = Np; b = blockIdx.x; bs = g_bs; }
    else { cnt = g_r_cnt; n = Nr; b = blockIdx.x - nbP; bs = g_bs + 128; }
    __shared__ int sm[256];
    int base = b * 4096, t = threadIdx.x;
    int sum = 0;
#pragma unroll
    for (int j = 0; j < 16; j++) {
        int i = base + t + 256 * j;
        if (i < n) sum += cnt[i];
    }
    sm[t] = sum; __syncthreads();
#pragma unroll
    for (int s = 128; s > 0; s >>= 1) {
        if (t < s) sm[t] += sm[t + s];
        __syncthreads();
    }
    if (t == 0) bs[b] = sm[0];
}

__global__ __launch_bounds__(128) void k_s2f(int nbP, int nbR) {
    int* bs = (blockIdx.x == 0) ? g_bs : g_bs + 128;
    int nb = (blockIdx.x == 0) ? nbP : nbR;
    __shared__ int sm[128];
    int t = threadIdx.x;
    int orig = (t < nb) ? bs[t] : 0;
    sm[t] = orig; __syncthreads();
#pragma unroll
    for (int o = 1; o < 128; o <<= 1) {
        int v = (t >= o) ? sm[t - o] : 0;
        __syncthreads();
        sm[t] += v;
        __syncthreads();
    }
    if (t < nb) bs[t] = sm[t] - orig;
}

__global__ __launch_bounds__(256) void k_s3f(int nbP, int Np, int Nr) {
    const int* cnt;
    int n, b;
    const int* bs;
    int *off, *pos;
    if ((int)blockIdx.x < nbP) {
        cnt = g_p_cnt; n = Np; b = blockIdx.x; bs = g_bs; off = g_p_off; pos = g_p_pos;
    } else {
        cnt = g_r_cnt; n = Nr; b = blockIdx.x - nbP; bs = g_bs + 128; off = g_r_off; pos = g_r_pos;
    }
    __shared__ int stage[4096];
    __shared__ int tsum[256];
    int base = b * 4096, t = threadIdx.x;
#pragma unroll
    for (int j = 0; j < 16; j++) {
        int i = base + t + 256 * j;
        stage[t + 256 * j] = (i < n) ? cnt[i] : 0;
    }
    __syncthreads();
    int loc[16];
    int s = 0;
#pragma unroll
    for (int j = 0; j < 16; j++) { loc[j] = s; s += stage[t * 16 + j]; }
    int orig = s;
    tsum[t] = s; __syncthreads();
#pragma unroll
    for (int o = 1; o < 256; o <<= 1) {
        int v = (t >= o) ? tsum[t - o] : 0;
        __syncthreads();
        tsum[t] += v;
        __syncthreads();
    }
    int toff = tsum[t] - orig + bs[b];
#pragma unroll
    for (int j = 0; j < 16; j++) {
        int i = base + t * 16 + j;
        if (i < n) { int o2 = toff + loc[j]; off[i] = o2; pos[i] = o2; }
    }
}

__global__ void k_fillf(const int* __restrict__ p_ei, int Ep,
                        const int* __restrict__ r_ei, int Er) {
    int e = blockIdx.x * blockDim.x + threadIdx.x;
    if (e < Ep) {
        int p = atomicAdd(&g_p_pos[p_ei[Ep + e]], 1);
        g_p_srcs[p] = p_ei[e];
    } else if (e < Ep + Er) {
        int e2 = e - Ep;
        int p = atomicAdd(&g_r_pos[r_ei[Er + e2]], 1);
        g_r_srcs[p] = r_ei[e2];
    }
}

// ---------------------------------------------------------------------------
// FUSED HMMA GEMM (p + r): bf16x2 (A hi/lo x B hi). CTA 256x64, warp m32n64.
// Epilogue: Y = bf16x2( xw * rsqrt(cnt+1) )
// ---------------------------------------------------------------------------
#define KC 64
#define BPAD 8
#define BSTR (KC + BPAD)

__global__ __launch_bounds__(256, 2) void k_gemm_fused(
    const float* __restrict__ Xp, const float* __restrict__ Xr,
    int Np, int Kp, int KpPad, int Nr, int Kr, int KrPad, int nbGp)
{
    const float* X;
    const __nv_bfloat16* Whi;
    const int* cnt;
    uint32_t* Y;
    int M, K, Kpad, bid;
    if ((int)blockIdx.x < nbGp) {
        X = Xp; Whi = g_pWhi; cnt = g_p_cnt; Y = g_p_y;
        M = Np; K = Kp; Kpad = KpPad; bid = blockIdx.x;
    } else {
        X = Xr; Whi = g_rWhi; cnt = g_r_cnt; Y = g_r_y;
        M = Nr; K = Kr; Kpad = KrPad; bid = blockIdx.x - nbGp;
    }

    __shared__ __align__(16) __nv_bfloat16 sB[2][64 * BSTR];
    uint32_t uB0 = smem_u32(sB[0]);
    uint32_t uB1 = smem_u32(sB[1]);

    int tid = threadIdx.x;
    int w = tid >> 5, lane = tid & 31;
    int g = lane >> 2, tg = lane & 3;

    int brow = tid >> 2;
    int bq   = (tid & 3) * 16;
    const __nv_bfloat16* bsrc = Whi + (size_t)brow * Kpad + bq;
    uint32_t bsto = (uint32_t)(brow * BSTR + bq) * 2;

    int bTile = lane >> 3;
    uint32_t bfoff = (uint32_t)(((bTile >> 1) * 8 + (lane & 7)) * BSTR + (bTile & 1) * 8) * 2;

    int rowBase = bid * 256 + w * 32;
    int rA = rowBase + g;
    const float* xbase = X + (size_t)rA * K;
    bool ok00 = (rA)      < M, ok01 = (rA + 8)  < M;
    bool ok10 = (rA + 16) < M, ok11 = (rA + 24) < M;
    size_t s8 = (size_t)8 * K, s16 = (size_t)16 * K, s24 = (size_t)24 * K;

    float d[2][8][4];
#pragma unroll
    for (int mt = 0; mt < 2; mt++)
#pragma unroll
        for (int nt = 0; nt < 8; nt++)
#pragma unroll
            for (int j = 0; j < 4; j++) d[mt][nt][j] = 0.0f;

    const float2 z2 = make_float2(0.f, 0.f);
    int nchunks = Kpad / KC;

    {
        const uint4* s = (const uint4*)bsrc;
        char* dstc = (char*)sB[0] + bsto;
        ((uint4*)dstc)[0] = s[0];
        ((uint4*)dstc)[1] = s[1];
    }
    __syncthreads();

    for (int ch = 0; ch < nchunks; ch++) {
        int k0 = ch * KC;
        uint32_t uBc = (ch & 1) ? uB1 : uB0;

        if (ch + 1 < nchunks) {
            const uint4* s = (const uint4*)(bsrc + (ch + 1) * KC);
            char* dstc = (char*)((ch & 1) ? sB[0] : sB[1]) + bsto;
            ((uint4*)dstc)[0] = s[0];
            ((uint4*)dstc)[1] = s[1];
        }

#pragma unroll
        for (int ks = 0; ks < KC / 16; ks++) {
            int kk = k0 + ks * 16 + tg * 2;
            bool kOK0 = (kk + 2) <= K;
            bool kOK1 = (kk + 10) <= K;

            uint32_t ah[2][4], al[2][4];
            {
                float2 f;
                f = (ok00 && kOK0) ? *(const float2*)(xbase + kk) : z2;
                cvt_hilo(f.x, f.y, ah[0][0], al[0][0]);
                f = (ok01 && kOK0) ? *(const float2*)(xbase + s8 + kk) : z2;
                cvt_hilo(f.x, f.y, ah[0][1], al[0][1]);
                f = (ok00 && kOK1) ? *(const float2*)(xbase + kk + 8) : z2;
                cvt_hilo(f.x, f.y, ah[0][2], al[0][2]);
                f = (ok01 && kOK1) ? *(const float2*)(xbase + s8 + kk + 8) : z2;
                cvt_hilo(f.x, f.y, ah[0][3], al[0][3]);
                f = (ok10 && kOK0) ? *(const float2*)(xbase + s16 + kk) : z2;
                cvt_hilo(f.x, f.y, ah[1][0], al[1][0]);
                f = (ok11 && kOK0) ? *(const float2*)(xbase + s24 + kk) : z2;
                cvt_hilo(f.x, f.y, ah[1][1], al[1][1]);
                f = (ok10 && kOK1) ? *(const float2*)(xbase + s16 + kk + 8) : z2;
                cvt_hilo(f.x, f.y, ah[1][2], al[1][2]);
                f = (ok11 && kOK1) ? *(const float2*)(xbase + s24 + kk + 8) : z2;
                cvt_hilo(f.x, f.y, ah[1][3], al[1][3]);
            }

#pragma unroll
            for (int np = 0; np < 4; np++) {
                uint32_t boffc = bfoff + (uint32_t)(np * 16 * BSTR + ks * 16) * 2;
                uint32_t bh[4];
                ldm_x4(bh, uBc + boffc);
#pragma unroll
                for (int mt = 0; mt < 2; mt++) {
                    mma_bf16(d[mt][np * 2],     ah[mt], bh[0], bh[1]);
                    mma_bf16(d[mt][np * 2],     al[mt], bh[0], bh[1]);
                    mma_bf16(d[mt][np * 2 + 1], ah[mt], bh[2], bh[3]);
                    mma_bf16(d[mt][np * 2 + 1], al[mt], bh[2], bh[3]);
                }
            }
        }
        __syncthreads();
    }

    // epilogue: Y = bf16x2(xw * rsqrt(cnt+1)); word index = nt*4 + tg
#pragma unroll
    for (int mt = 0; mt < 2; mt++) {
#pragma unroll
        for (int rs = 0; rs < 2; rs++) {
            int row = rowBase + mt * 16 + g + rs * 8;
            if (row < M) {
                float dv = rsqrtf((float)(cnt[row] + 1));
                uint32_t* yp = Y + (size_t)row * 32;
#pragma unroll
                for (int nt = 0; nt < 8; nt++) {
                    __nv_bfloat162 h = __float22bfloat162_rn(
                        make_float2(d[mt][nt][2 * rs] * dv, d[mt][nt][2 * rs + 1] * dv));
                    yp[nt * 4 + tg] = *(uint32_t*)&h;
                }
            }
        }
    }
}

// ---------------------------------------------------------------------------
// FUSED gather + relu + mean-pool (warp run-sums), y in bf16x2.
// Each lane handles 2 cols = 1 word.
// ---------------------------------------------------------------------------
#define GP_CH 32
__global__ __launch_bounds__(256) void k_gather_fused(
    const int* __restrict__ p_bat, const float* __restrict__ p_b,
    const int* __restrict__ r_bat, const float* __restrict__ r_b,
    int Np, int Nr, int wP)
{
    int warp = blockIdx.x * 8 + (threadIdx.x >> 5);
    int lane = threadIdx.x & 31;

    const uint32_t* y; const int *off, *cnt, *srcs, *batch; const float* bias;
    int n, n0, colbase, cntbase;
    if (warp < wP) {
        y = g_p_y; off = g_p_off; cnt = g_p_cnt; srcs = g_p_srcs;
        batch = p_bat; bias = p_b; n = Np; n0 = warp * GP_CH; colbase = 0; cntbase = 0;
    } else {
        y = g_r_y; off = g_r_off; cnt = g_r_cnt; srcs = g_r_srcs;
        batch = r_bat; bias = r_b; n = Nr; n0 = (warp - wP) * GP_CH; colbase = 64; cntbase = NG;
    }
    if (n0 >= n) return;
    int nend = min(n0 + GP_CH, n);
    float2 b = *(const float2*)(bias + lane * 2);

    float2 run = make_float2(0.f, 0.f);
    float rc = 0.f;
    int curg = -1;

    for (int nn = n0; nn < nend; nn++) {
        int j = off[nn];
        int deg = cnt[nn];
        int e = j + deg;
        uint32_t u = y[(size_t)nn * 32 + lane];
        float2 a = __bfloat1622float2(*(__nv_bfloat162*)&u);
        int s0 = (j < e) ? srcs[j] : 0;
        int s1 = (j + 1 < e) ? srcs[j + 1] : 0;
        for (; j + 1 < e; j += 2) {
            uint32_t u0 = y[(size_t)s0 * 32 + lane];
            uint32_t u1 = y[(size_t)s1 * 32 + lane];
            s0 = (j + 2 < e) ? srcs[j + 2] : 0;
            s1 = (j + 3 < e) ? srcs[j + 3] : 0;
            float2 v0 = __bfloat1622float2(*(__nv_bfloat162*)&u0);
            float2 v1 = __bfloat1622float2(*(__nv_bfloat162*)&u1);
            a.x += v0.x + v1.x;
            a.y += v0.y + v1.y;
        }
        if (j < e) {
            uint32_t u0 = y[(size_t)s0 * 32 + lane];
            float2 v = __bfloat1622float2(*(__nv_bfloat162*)&u0);
            a.x += v.x; a.y += v.y;
        }
        float dv = rsqrtf((float)(deg + 1));
        float vx = fmaxf(dv * a.x + b.x, 0.0f);
        float vy = fmaxf(dv * a.y + b.y, 0.0f);
        int gph = batch[nn];
        if (gph != curg) {
            if (curg >= 0) {
                float* pp = &g_pool[curg * 128 + colbase + lane * 2];
                asm volatile("red.global.add.v2.f32 [%0], {%1,%2};"
                             :: "l"(pp), "f"(run.x), "f"(run.y) : "memory");
                if (lane == 0) {
                    float* cp = &g_cnt[cntbase + curg];
                    asm volatile("red.global.add.f32 [%0], %1;" :: "l"(cp), "f"(rc) : "memory");
                }
            }
            curg = gph; run = make_float2(0.f, 0.f); rc = 0.f;
        }
        run.x += vx; run.y += vy; rc += 1.f;
    }
    if (curg >= 0) {
        float* pp = &g_pool[curg * 128 + colbase + lane * 2];
        asm volatile("red.global.add.v2.f32 [%0], {%1,%2};"
                     :: "l"(pp), "f"(run.x), "f"(run.y) : "memory");
        if (lane == 0) {
            float* cp = &g_cnt[cntbase + curg];
            asm volatile("red.global.add.f32 [%0], %1;" :: "l"(cp), "f"(rc) : "memory");
        }
    }
}

__global__ void k_final(const float* __restrict__ linW, const float* __restrict__ linb,
                        float* __restrict__ out) {
    int t = threadIdx.x;
    int g = t >> 1, c = t & 1;
    float cp = fmaxf(g_cnt[g], 1.0f);
    float cr = fmaxf(g_cnt[NG + g], 1.0f);
    float s = linb[c];
#pragma unroll 8
    for (int j = 0; j < 64; j++)  s += (g_pool[g * 128 + j] / cp) * linW[j * 2 + c];
#pragma unroll 8
    for (int j = 64; j < 128; j++) s += (g_pool[g * 128 + j] / cr) * linW[j * 2 + c];
    out[g * 2 + c] = s;
}

// ---------------------------------------------------------------------------
extern "C" void kernel_launch(void* const* d_in, const int* in_sizes, int n_in,
                              void* d_out, int out_size) {
    const float* p_x   = (const float*)d_in[0];
    const int*   p_ei  = (const int*)d_in[1];
    const int*   p_bat = (const int*)d_in[2];
    const float* r_x   = (const float*)d_in[3];
    const int*   r_ei  = (const int*)d_in[4];
    const int*   r_bat = (const int*)d_in[5];
    const float* p_W   = (const float*)d_in[6];
    const float* p_b   = (const float*)d_in[7];
    const float* r_W   = (const float*)d_in[8];
    const float* r_b   = (const float*)d_in[9];
    const float* linW  = (const float*)d_in[10];
    const float* linb  = (const float*)d_in[11];
    float* out = (float*)d_out;

    int Np = in_sizes[2];
    int Kp = in_sizes[0] / Np;
    int Ep = in_sizes[1] / 2;
    int Nr = in_sizes[5];
    int Kr = in_sizes[3] / Nr;
    int Er = in_sizes[4] / 2;
    int KpPad = ((Kp + 63) / 64) * 64;
    int KrPad = ((Kr + 63) / 64) * 64;

    int *p_cnt, *r_cnt;
    cudaGetSymbolAddress((void**)&p_cnt, g_p_cnt);
    cudaGetSymbolAddress((void**)&r_cnt, g_r_cnt);

    int nmax = (Np > Nr ? Np : Nr);
    if (nmax < NG * 128) nmax = NG * 128;
    if (nmax < 64 * KpPad) nmax = 64 * KpPad;
    if (nmax < 64 * KrPad) nmax = 64 * KrPad;

    int nbP = (Np + 4095) / 4096;
    int nbR = (Nr + 4095) / 4096;
    int nbGp = (Np + 255) / 256;
    int nbGr = (Nr + 255) / 256;

    // 1-3
    k_init<<<(nmax + 255) / 256, 256>>>(Np, Nr, p_W, r_W, Kp, KpPad, Kr, KrPad);
    k_count<<<(Ep + 255) / 256, 256>>>(p_ei + Ep, Ep, p_cnt);
    k_count<<<(Er + 255) / 256, 256>>>(r_ei + Er, Er, r_cnt);

    // 4: fused GEMM (profiled slot)
    k_gemm_fused<<<nbGp + nbGr, 256>>>(p_x, r_x, Np, Kp, KpPad, Nr, Kr, KrPad, nbGp);

    // 5-8: fused CSR build
    k_s1f<<<nbP + nbR, 256>>>(nbP, Np, Nr);
    k_s2f<<<2, 128>>>(nbP, nbR);
    k_s3f<<<nbP + nbR, 256>>>(nbP, Np, Nr);
    k_fillf<<<(Ep + Er + 255) / 256, 256>>>(p_ei, Ep, r_ei, Er);

    // 9: fused gather+pool
    int wP = (Np + GP_CH - 1) / GP_CH;
    int wR = (Nr + GP_CH - 1) / GP_CH;
    k_gather_fused<<<(wP + wR + 7) / 8, 256>>>(p_bat, p_b, r_bat, r_b, Np, Nr, wP);

    // 10
    k_final<<<1, 256>>>(linW, linb, out);
}

// round 17
// speedup vs baseline: 1.4443x; 1.4443x over previous
#include <cuda_runtime.h>
#include <cuda_bf16.h>
#include <cstdint>

#define NG 128
#define NPMAX 200000
#define NRMAX 400000
#define EMAX 2000000

// ---- static scratch ----
__device__ __align__(16) float g_p_y  [NPMAX * 64];
__device__ __align__(16) float g_r_y  [NRMAX * 64];
__device__ int   g_p_cnt[NPMAX];
__device__ int   g_r_cnt[NRMAX];
__device__ int   g_p_off[NPMAX];
__device__ int   g_r_off[NRMAX];
__device__ int   g_p_pos[NPMAX];
__device__ int   g_r_pos[NRMAX];
__device__ int   g_p_srcs[EMAX];
__device__ int   g_r_srcs[EMAX];
__device__ int   g_bs[256];          // [0..127] p-blocks, [128..255] r-blocks
__device__ float g_pool[NG * 128];
__device__ float g_cnt[2 * NG];
__device__ __align__(16) __nv_bfloat16 g_pWhi[64 * 1280];
__device__ __align__(16) __nv_bfloat16 g_rWhi[64 * 128];

__device__ __forceinline__ uint32_t smem_u32(const void* p) {
    uint32_t a;
    asm("{ .reg .u64 t; cvta.to.shared.u64 t, %1; cvt.u32.u64 %0, t; }" : "=r"(a) : "l"(p));
    return a;
}

__device__ __forceinline__ void ldm_x4(uint32_t* r, uint32_t addr) {
    asm volatile("ldmatrix.sync.aligned.m8n8.x4.shared.b16 {%0,%1,%2,%3}, [%4];"
                 : "=r"(r[0]), "=r"(r[1]), "=r"(r[2]), "=r"(r[3]) : "r"(addr));
}

__device__ __forceinline__ void mma_bf16(float* d, const uint32_t* a, uint32_t b0, uint32_t b1) {
    asm volatile(
        "mma.sync.aligned.m16n8k16.row.col.f32.bf16.bf16.f32 "
        "{%0,%1,%2,%3}, {%4,%5,%6,%7}, {%8,%9}, {%0,%1,%2,%3};"
        : "+f"(d[0]), "+f"(d[1]), "+f"(d[2]), "+f"(d[3])
        : "r"(a[0]), "r"(a[1]), "r"(a[2]), "r"(a[3]), "r"(b0), "r"(b1));
}

__device__ __forceinline__ uint32_t cvt_hi(float x, float y) {
    __nv_bfloat162 h = __float22bfloat162_rn(make_float2(x, y));
    return *(uint32_t*)&h;
}

// ---------------------------------------------------------------------------
__global__ void k_init(int np, int nr,
                       const float* __restrict__ pW, const float* __restrict__ rW,
                       int Kp, int KpPad, int Kr, int KrPad) {
    int i = blockIdx.x * blockDim.x + threadIdx.x;
    if (i < np) g_p_cnt[i] = 0;
    if (i < nr) g_r_cnt[i] = 0;
    if (i < NG * 128) g_pool[i] = 0.0f;
    if (i < 2 * NG) g_cnt[i] = 0.0f;
    if (i < 64 * KpPad) {
        int n = i / KpPad, k = i % KpPad;
        g_pWhi[i] = __float2bfloat16_rn((k < Kp) ? pW[k * 64 + n] : 0.0f);
    }
    if (i < 64 * KrPad) {
        int n = i / KrPad, k = i % KrPad;
        g_rWhi[i] = __float2bfloat16_rn((k < Kr) ? rW[k * 64 + n] : 0.0f);
    }
}

__global__ void k_count(const int* __restrict__ dst, int E, int* __restrict__ cnt) {
    int e = blockIdx.x * blockDim.x + threadIdx.x;
    if (e < E) atomicAdd(&cnt[dst[e]], 1);
}

// ---------------------------------------------------------------------------
// fused exclusive scans
// ---------------------------------------------------------------------------
__global__ __launch_bounds__(256) void k_s1f(int nbP, int Np, int Nr) {
    const int* cnt;
    int n, b;
    int* bs;
    if ((int)blockIdx.x < nbP) { cnt = g_p_cnt; n = Np; b = blockIdx.x; bs = g_bs; }
    else { cnt = g_r_cnt; n = Nr; b = blockIdx.x - nbP; bs = g_bs + 128; }
    __shared__ int sm[256];
    int base = b * 4096, t = threadIdx.x;
    int sum = 0;
#pragma unroll
    for (int j = 0; j < 16; j++) {
        int i = base + t + 256 * j;
        if (i < n) sum += cnt[i];
    }
    sm[t] = sum; __syncthreads();
#pragma unroll
    for (int s = 128; s > 0; s >>= 1) {
        if (t < s) sm[t] += sm[t + s];
        __syncthreads();
    }
    if (t == 0) bs[b] = sm[0];
}

__global__ __launch_bounds__(128) void k_s2f(int nbP, int nbR) {
    int* bs = (blockIdx.x == 0) ? g_bs : g_bs + 128;
    int nb = (blockIdx.x == 0) ? nbP : nbR;
    __shared__ int sm[128];
    int t = threadIdx.x;
    int orig = (t < nb) ? bs[t] : 0;
    sm[t] = orig; __syncthreads();
#pragma unroll
    for (int o = 1; o < 128; o <<= 1) {
        int v = (t >= o) ? sm[t - o] : 0;
        __syncthreads();
        sm[t] += v;
        __syncthreads();
    }
    if (t < nb) bs[t] = sm[t] - orig;
}

__global__ __launch_bounds__(256) void k_s3f(int nbP, int Np, int Nr) {
    const int* cnt;
    int n, b;
    const int* bs;
    int *off, *pos;
    if ((int)blockIdx.x < nbP) {
        cnt = g_p_cnt; n = Np; b = blockIdx.x; bs = g_bs; off = g_p_off; pos = g_p_pos;
    } else {
        cnt = g_r_cnt; n = Nr; b = blockIdx.x - nbP; bs = g_bs + 128; off = g_r_off; pos = g_r_pos;
    }
    __shared__ int stage[4096];
    __shared__ int tsum[256];
    int base = b * 4096, t = threadIdx.x;
#pragma unroll
    for (int j = 0; j < 16; j++) {
        int i = base + t + 256 * j;
        stage[t + 256 * j] = (i < n) ? cnt[i] : 0;
    }
    __syncthreads();
    int loc[16];
    int s = 0;
#pragma unroll
    for (int j = 0; j < 16; j++) { loc[j] = s; s += stage[t * 16 + j]; }
    int orig = s;
    tsum[t] = s; __syncthreads();
#pragma unroll
    for (int o = 1; o < 256; o <<= 1) {
        int v = (t >= o) ? tsum[t - o] : 0;
        __syncthreads();
        tsum[t] += v;
        __syncthreads();
    }
    int toff = tsum[t] - orig + bs[b];
#pragma unroll
    for (int j = 0; j < 16; j++) {
        int i = base + t * 16 + j;
        if (i < n) { int o2 = toff + loc[j]; off[i] = o2; pos[i] = o2; }
    }
}

__global__ void k_fillf(const int* __restrict__ p_ei, int Ep,
                        const int* __restrict__ r_ei, int Er) {
    int e = blockIdx.x * blockDim.x + threadIdx.x;
    if (e < Ep) {
        int p = atomicAdd(&g_p_pos[p_ei[Ep + e]], 1);
        g_p_srcs[p] = p_ei[e];
    } else if (e < Ep + Er) {
        int e2 = e - Ep;
        int p = atomicAdd(&g_r_pos[r_ei[Er + e2]], 1);
        g_r_srcs[p] = r_ei[e2];
    }
}

// ---------------------------------------------------------------------------
// FUSED HMMA GEMM (p + r): pure bf16 (A hi x B hi, single MMA per tile).
// CTA 256x64, warp m32n64, 2 CTAs/SM. Epilogue: Y = xw * rsqrt(cnt+1) (fp32).
// ---------------------------------------------------------------------------
#define KC 64
#define BPAD 8
#define BSTR (KC + BPAD)

__global__ __launch_bounds__(256, 2) void k_gemm_fused(
    const float* __restrict__ Xp, const float* __restrict__ Xr,
    int Np, int Kp, int KpPad, int Nr, int Kr, int KrPad, int nbGp)
{
    const float* X;
    const __nv_bfloat16* Whi;
    const int* cnt;
    float* Y;
    int M, K, Kpad, bid;
    if ((int)blockIdx.x < nbGp) {
        X = Xp; Whi = g_pWhi; cnt = g_p_cnt; Y = g_p_y;
        M = Np; K = Kp; Kpad = KpPad; bid = blockIdx.x;
    } else {
        X = Xr; Whi = g_rWhi; cnt = g_r_cnt; Y = g_r_y;
        M = Nr; K = Kr; Kpad = KrPad; bid = blockIdx.x - nbGp;
    }

    __shared__ __align__(16) __nv_bfloat16 sB[2][64 * BSTR];
    uint32_t uB0 = smem_u32(sB[0]);
    uint32_t uB1 = smem_u32(sB[1]);

    int tid = threadIdx.x;
    int w = tid >> 5, lane = tid & 31;
    int g = lane >> 2, tg = lane & 3;

    int brow = tid >> 2;
    int bq   = (tid & 3) * 16;
    const __nv_bfloat16* bsrc = Whi + (size_t)brow * Kpad + bq;
    uint32_t bsto = (uint32_t)(brow * BSTR + bq) * 2;

    int bTile = lane >> 3;
    uint32_t bfoff = (uint32_t)(((bTile >> 1) * 8 + (lane & 7)) * BSTR + (bTile & 1) * 8) * 2;

    int rowBase = bid * 256 + w * 32;
    int rA = rowBase + g;
    const float* xbase = X + (size_t)rA * K;
    bool ok00 = (rA)      < M, ok01 = (rA + 8)  < M;
    bool ok10 = (rA + 16) < M, ok11 = (rA + 24) < M;
    size_t s8 = (size_t)8 * K, s16 = (size_t)16 * K, s24 = (size_t)24 * K;

    float d[2][8][4];
#pragma unroll
    for (int mt = 0; mt < 2; mt++)
#pragma unroll
        for (int nt = 0; nt < 8; nt++)
#pragma unroll
            for (int j = 0; j < 4; j++) d[mt][nt][j] = 0.0f;

    const float2 z2 = make_float2(0.f, 0.f);
    int nchunks = Kpad / KC;

    {
        const uint4* s = (const uint4*)bsrc;
        char* dstc = (char*)sB[0] + bsto;
        ((uint4*)dstc)[0] = s[0];
        ((uint4*)dstc)[1] = s[1];
    }
    __syncthreads();

    for (int ch = 0; ch < nchunks; ch++) {
        int k0 = ch * KC;
        uint32_t uBc = (ch & 1) ? uB1 : uB0;

        if (ch + 1 < nchunks) {
            const uint4* s = (const uint4*)(bsrc + (ch + 1) * KC);
            char* dstc = (char*)((ch & 1) ? sB[0] : sB[1]) + bsto;
            ((uint4*)dstc)[0] = s[0];
            ((uint4*)dstc)[1] = s[1];
        }

#pragma unroll
        for (int ks = 0; ks < KC / 16; ks++) {
            int kk = k0 + ks * 16 + tg * 2;
            bool kOK0 = (kk + 2) <= K;
            bool kOK1 = (kk + 10) <= K;

            uint32_t ah[2][4];
            {
                float2 f;
                f = (ok00 && kOK0) ? *(const float2*)(xbase + kk) : z2;
                ah[0][0] = cvt_hi(f.x, f.y);
                f = (ok01 && kOK0) ? *(const float2*)(xbase + s8 + kk) : z2;
                ah[0][1] = cvt_hi(f.x, f.y);
                f = (ok00 && kOK1) ? *(const float2*)(xbase + kk + 8) : z2;
                ah[0][2] = cvt_hi(f.x, f.y);
                f = (ok01 && kOK1) ? *(const float2*)(xbase + s8 + kk + 8) : z2;
                ah[0][3] = cvt_hi(f.x, f.y);
                f = (ok10 && kOK0) ? *(const float2*)(xbase + s16 + kk) : z2;
                ah[1][0] = cvt_hi(f.x, f.y);
                f = (ok11 && kOK0) ? *(const float2*)(xbase + s24 + kk) : z2;
                ah[1][1] = cvt_hi(f.x, f.y);
                f = (ok10 && kOK1) ? *(const float2*)(xbase + s16 + kk + 8) : z2;
                ah[1][2] = cvt_hi(f.x, f.y);
                f = (ok11 && kOK1) ? *(const float2*)(xbase + s24 + kk + 8) : z2;
                ah[1][3] = cvt_hi(f.x, f.y);
            }

#pragma unroll
            for (int np = 0; np < 4; np++) {
                uint32_t boffc = bfoff + (uint32_t)(np * 16 * BSTR + ks * 16) * 2;
                uint32_t bh[4];
                ldm_x4(bh, uBc + boffc);
#pragma unroll
                for (int mt = 0; mt < 2; mt++) {
                    mma_bf16(d[mt][np * 2],     ah[mt], bh[0], bh[1]);
                    mma_bf16(d[mt][np * 2 + 1], ah[mt], bh[2], bh[3]);
                }
            }
        }
        __syncthreads();
    }

#pragma unroll
    for (int mt = 0; mt < 2; mt++) {
#pragma unroll
        for (int rs = 0; rs < 2; rs++) {
            int row = rowBase + mt * 16 + g + rs * 8;
            if (row < M) {
                float dv = rsqrtf((float)(cnt[row] + 1));
                float* yp = Y + (size_t)row * 64;
#pragma unroll
                for (int nt = 0; nt < 8; nt++) {
                    int col = nt * 8 + 2 * tg;
                    *(float2*)(yp + col) = make_float2(d[mt][nt][2 * rs] * dv,
                                                       d[mt][nt][2 * rs + 1] * dv);
                }
            }
        }
    }
}

// ---------------------------------------------------------------------------
// FUSED gather + relu + mean-pool (warp run-sums), y fp32.
// ---------------------------------------------------------------------------
#define GP_CH 32
__global__ __launch_bounds__(256) void k_gather_fused(
    const int* __restrict__ p_bat, const float* __restrict__ p_b,
    const int* __restrict__ r_bat, const float* __restrict__ r_b,
    int Np, int Nr, int wP)
{
    int warp = blockIdx.x * 8 + (threadIdx.x >> 5);
    int lane = threadIdx.x & 31;

    const float* y; const int *off, *cnt, *srcs, *batch; const float* bias;
    int n, n0, colbase, cntbase;
    if (warp < wP) {
        y = g_p_y; off = g_p_off; cnt = g_p_cnt; srcs = g_p_srcs;
        batch = p_bat; bias = p_b; n = Np; n0 = warp * GP_CH; colbase = 0; cntbase = 0;
    } else {
        y = g_r_y; off = g_r_off; cnt = g_r_cnt; srcs = g_r_srcs;
        batch = r_bat; bias = r_b; n = Nr; n0 = (warp - wP) * GP_CH; colbase = 64; cntbase = NG;
    }
    if (n0 >= n) return;
    int nend = min(n0 + GP_CH, n);
    int c = lane * 2;
    float2 b = *(const float2*)(bias + c);

    float2 run = make_float2(0.f, 0.f);
    float rc = 0.f;
    int curg = -1;

    for (int nn = n0; nn < nend; nn++) {
        int j = off[nn];
        int deg = cnt[nn];
        int e = j + deg;
        float2 a = *(const float2*)(y + (size_t)nn * 64 + c);
        int s0 = (j < e) ? srcs[j] : 0;
        int s1 = (j + 1 < e) ? srcs[j + 1] : 0;
        for (; j + 1 < e; j += 2) {
            float2 v0 = *(const float2*)(y + (size_t)s0 * 64 + c);
            float2 v1 = *(const float2*)(y + (size_t)s1 * 64 + c);
            s0 = (j + 2 < e) ? srcs[j + 2] : 0;
            s1 = (j + 3 < e) ? srcs[j + 3] : 0;
            a.x += v0.x + v1.x;
            a.y += v0.y + v1.y;
        }
        if (j < e) {
            float2 v = *(const float2*)(y + (size_t)s0 * 64 + c);
            a.x += v.x; a.y += v.y;
        }
        float dv = rsqrtf((float)(deg + 1));
        float vx = fmaxf(dv * a.x + b.x, 0.0f);
        float vy = fmaxf(dv * a.y + b.y, 0.0f);
        int gph = batch[nn];
        if (gph != curg) {
            if (curg >= 0) {
                float* pp = &g_pool[curg * 128 + colbase + c];
                asm volatile("red.global.add.v2.f32 [%0], {%1,%2};"
                             :: "l"(pp), "f"(run.x), "f"(run.y) : "memory");
                if (lane == 0) {
                    float* cp = &g_cnt[cntbase + curg];
                    asm volatile("red.global.add.f32 [%0], %1;" :: "l"(cp), "f"(rc) : "memory");
                }
            }
            curg = gph; run = make_float2(0.f, 0.f); rc = 0.f;
        }
        run.x += vx; run.y += vy; rc += 1.f;
    }
    if (curg >= 0) {
        float* pp = &g_pool[curg * 128 + colbase + c];
        asm volatile("red.global.add.v2.f32 [%0], {%1,%2};"
                     :: "l"(pp), "f"(run.x), "f"(run.y) : "memory");
        if (lane == 0) {
            float* cp = &g_cnt[cntbase + curg];
            asm volatile("red.global.add.f32 [%0], %1;" :: "l"(cp), "f"(rc) : "memory");
        }
    }
}

__global__ void k_final(const float* __restrict__ linW, const float* __restrict__ linb,
                        float* __restrict__ out) {
    int t = threadIdx.x;
    int g = t >> 1, c = t & 1;
    float cp = fmaxf(g_cnt[g], 1.0f);
    float cr = fmaxf(g_cnt[NG + g], 1.0f);
    float s = linb[c];
#pragma unroll 8
    for (int j = 0; j < 64; j++)  s += (g_pool[g * 128 + j] / cp) * linW[j * 2 + c];
#pragma unroll 8
    for (int j = 64; j < 128; j++) s += (g_pool[g * 128 + j] / cr) * linW[j * 2 + c];
    out[g * 2 + c] = s;
}

// ---------------------------------------------------------------------------
extern "C" void kernel_launch(void* const* d_in, const int* in_sizes, int n_in,
                              void* d_out, int out_size) {
    const float* p_x   = (const float*)d_in[0];
    const int*   p_ei  = (const int*)d_in[1];
    const int*   p_bat = (const int*)d_in[2];
    const float* r_x   = (const float*)d_in[3];
    const int*   r_ei  = (const int*)d_in[4];
    const int*   r_bat = (const int*)d_in[5];
    const float* p_W   = (const float*)d_in[6];
    const float* p_b   = (const float*)d_in[7];
    const float* r_W   = (const float*)d_in[8];
    const float* r_b   = (const float*)d_in[9];
    const float* linW  = (const float*)d_in[10];
    const float* linb  = (const float*)d_in[11];
    float* out = (float*)d_out;

    int Np = in_sizes[2];
    int Kp = in_sizes[0] / Np;
    int Ep = in_sizes[1] / 2;
    int Nr = in_sizes[5];
    int Kr = in_sizes[3] / Nr;
    int Er = in_sizes[4] / 2;
    int KpPad = ((Kp + 63) / 64) * 64;
    int KrPad = ((Kr + 63) / 64) * 64;

    int *p_cnt, *r_cnt;
    cudaGetSymbolAddress((void**)&p_cnt, g_p_cnt);
    cudaGetSymbolAddress((void**)&r_cnt, g_r_cnt);

    int nmax = (Np > Nr ? Np : Nr);
    if (nmax < NG * 128) nmax = NG * 128;
    if (nmax < 64 * KpPad) nmax = 64 * KpPad;
    if (nmax < 64 * KrPad) nmax = 64 * KrPad;

    int nbP = (Np + 4095) / 4096;
    int nbR = (Nr + 4095) / 4096;
    int nbGp = (Np + 255) / 256;
    int nbGr = (Nr + 255) / 256;

    // 1-3
    k_init<<<(nmax + 255) / 256, 256>>>(Np, Nr, p_W, r_W, Kp, KpPad, Kr, KrPad);
    k_count<<<(Ep + 255) / 256, 256>>>(p_ei + Ep, Ep, p_cnt);
    k_count<<<(Er + 255) / 256, 256>>>(r_ei + Er, Er, r_cnt);

    // 4: fused GEMM (profiled slot)
    k_gemm_fused<<<nbGp + nbGr, 256>>>(p_x, r_x, Np, Kp, KpPad, Nr, Kr, KrPad, nbGp);

    // 5-8: fused CSR build
    k_s1f<<<nbP + nbR, 256>>>(nbP, Np, Nr);
    k_s2f<<<2, 128>>>(nbP, nbR);
    k_s3f<<<nbP + nbR, 256>>>(nbP, Np, Nr);
    k_fillf<<<(Ep + Er + 255) / 256, 256>>>(p_ei, Ep, r_ei, Er);

    // 9: fused gather+pool
    int wP = (Np + GP_CH - 1) / GP_CH;
    int wR = (Nr + GP_CH - 1) / GP_CH;
    k_gather_fused<<<(wP + wR + 7) / 8, 256>>>(p_bat, p_b, r_bat, r_b, Np, Nr, wP);

    // 10
    k_final<<<1, 256>>>(linW, linb, out);
}